// round 4
// baseline (speedup 1.0000x reference)
#include <cuda_runtime.h>
#include <cuda_bf16.h>

#define N_NODES 50000
#define N_EDGES 500000
#define HIDDEN  128
#define HEADS   8
#define HDIM    16

// ---------------- static device scratch ----------------
__device__ float g_q[N_NODES * HIDDEN];     // q; overwritten in-place with hupd by k_node
__device__ float g_k[N_NODES * HIDDEN];     // k; later reused as t1 (silu output)
__device__ float g_v[N_NODES * HIDDEN];
__device__ float g_ex[N_EDGES * HEADS];     // exp(logit) per (edge, head)
__device__ float g_disp[N_NODES * 3];
__device__ int   g_cnt[N_NODES];            // degree histogram
__device__ int   g_off[N_NODES + 1];        // CSR offsets
__device__ int   g_cur[N_NODES];            // scatter cursors
__device__ int   g_perm[N_EDGES];           // edge ids sorted by src

// ---------------- sort: zero counters ----------------
__global__ void k_zero() {
    int i = blockIdx.x * blockDim.x + threadIdx.x;
    if (i < N_NODES) g_cnt[i] = 0;
}

// ---------------- sort: histogram ----------------
__global__ void k_hist(const int* __restrict__ src) {
    int e = blockIdx.x * blockDim.x + threadIdx.x;
    if (e < N_EDGES) atomicAdd(&g_cnt[src[e]], 1);
}

// ---------------- sort: single-block scan (1024 threads, chunk 49) ----------------
__global__ void k_scan() {
    __shared__ int sm[1024];
    const int CH = (N_NODES + 1023) / 1024;   // 49
    int t = threadIdx.x;
    int beg = t * CH, end = min(beg + CH, N_NODES);
    int s = 0;
    for (int i = beg; i < end; i++) s += g_cnt[i];
    sm[t] = s;
    __syncthreads();
    // Hillis-Steele inclusive scan
    for (int off = 1; off < 1024; off <<= 1) {
        int u = (t >= off) ? sm[t - off] : 0;
        __syncthreads();
        sm[t] += u;
        __syncthreads();
    }
    int base = sm[t] - s;                     // exclusive prefix
    for (int i = beg; i < end; i++) {
        g_off[i] = base;
        g_cur[i] = base;
        base += g_cnt[i];
    }
    if (t == 1023) g_off[N_NODES] = N_EDGES;
}

// ---------------- sort: scatter edge ids ----------------
__global__ void k_scatter(const int* __restrict__ src) {
    int e = blockIdx.x * blockDim.x + threadIdx.x;
    if (e >= N_EDGES) return;
    int pos = atomicAdd(&g_cur[src[e]], 1);
    g_perm[pos] = e;
}

// ---------------- 128x128-tile fp32 GEMM, 256 thr, 8x8 microtile ----------------
// EPI: 0 = plain, 1 = +residual, 2 = silu
#define KC 16

template <int EPI>
__global__ __launch_bounds__(256, 2) void gemm128(
    const float* __restrict__ A,
    const float* __restrict__ B0, const float* __restrict__ B1, const float* __restrict__ B2,
    const float* __restrict__ bias0, const float* __restrict__ bias1, const float* __restrict__ bias2,
    const float* __restrict__ res,
    float* __restrict__ out0, float* __restrict__ out1, float* __restrict__ out2,
    int M)
{
    __shared__ float As[KC][132];
    __shared__ float Bs[KC][HIDDEN];

    const float* B    = (blockIdx.y == 0) ? B0    : (blockIdx.y == 1) ? B1    : B2;
    const float* bias = (blockIdx.y == 0) ? bias0 : (blockIdx.y == 1) ? bias1 : bias2;
    float*       out  = (blockIdx.y == 0) ? out0  : (blockIdx.y == 1) ? out1  : out2;

    const int t   = threadIdx.x;
    const int tx  = t & 15;
    const int ty  = t >> 4;
    const int row0 = blockIdx.x * 128;

    float acc[8][8];
#pragma unroll
    for (int i = 0; i < 8; i++)
#pragma unroll
        for (int j = 0; j < 8; j++) acc[i][j] = 0.f;

    for (int kt = 0; kt < HIDDEN; kt += KC) {
#pragma unroll
        for (int it = 0; it < 2; it++) {
            int idx = t + it * 256;
            int r   = idx >> 2;
            int c4  = idx & 3;
            float4 val = make_float4(0.f, 0.f, 0.f, 0.f);
            int gr = row0 + r;
            if (gr < M) val = *(const float4*)(A + gr * HIDDEN + kt + c4 * 4);
            As[c4 * 4 + 0][r] = val.x;
            As[c4 * 4 + 1][r] = val.y;
            As[c4 * 4 + 2][r] = val.z;
            As[c4 * 4 + 3][r] = val.w;
        }
#pragma unroll
        for (int it = 0; it < 2; it++) {
            int idx = t + it * 256;
            int r   = idx >> 5;
            int c4  = idx & 31;
            *(float4*)(&Bs[r][c4 * 4]) = *(const float4*)(B + (kt + r) * HIDDEN + c4 * 4);
        }
        __syncthreads();

#pragma unroll
        for (int kk = 0; kk < KC; kk++) {
            float4 a0 = *(float4*)(&As[kk][ty * 8]);
            float4 a1 = *(float4*)(&As[kk][ty * 8 + 4]);
            float4 b0 = *(float4*)(&Bs[kk][tx * 8]);
            float4 b1 = *(float4*)(&Bs[kk][tx * 8 + 4]);
            float a[8] = {a0.x, a0.y, a0.z, a0.w, a1.x, a1.y, a1.z, a1.w};
            float b[8] = {b0.x, b0.y, b0.z, b0.w, b1.x, b1.y, b1.z, b1.w};
#pragma unroll
            for (int i = 0; i < 8; i++)
#pragma unroll
                for (int j = 0; j < 8; j++) acc[i][j] = fmaf(a[i], b[j], acc[i][j]);
        }
        __syncthreads();
    }

#pragma unroll
    for (int i = 0; i < 8; i++) {
        int gr = row0 + ty * 8 + i;
        if (gr >= M) continue;
#pragma unroll
        for (int jj = 0; jj < 2; jj++) {
            int col = tx * 8 + jj * 4;
            float z[4];
#pragma unroll
            for (int q = 0; q < 4; q++) z[q] = acc[i][jj * 4 + q] + bias[col + q];
            if (EPI == 1) {
                float4 r4 = *(const float4*)(res + gr * HIDDEN + col);
                z[0] += r4.x; z[1] += r4.y; z[2] += r4.z; z[3] += r4.w;
            }
            if (EPI == 2) {
#pragma unroll
                for (int q = 0; q < 4; q++) z[q] = z[q] / (1.f + __expf(-z[q]));
            }
            *(float4*)(out + gr * HIDDEN + col) = make_float4(z[0], z[1], z[2], z[3]);
        }
    }
}

// ---------------- warp-per-node edge processing: no atomics ----------------
// Lane = h*4 + c (8 heads x 4 float4 chunks). Loop 1: attention sums + U accum.
// Loop 2: displacement. hupd written in-place over g_q.
__global__ __launch_bounds__(256) void k_node(
    const int* __restrict__ dst, const float* __restrict__ dist,
    const float* __restrict__ x,
    const float* __restrict__ Wd, const float* __restrict__ bd)
{
    int warp = (blockIdx.x * blockDim.x + threadIdx.x) >> 5;
    if (warp >= N_NODES) return;
    const int n    = warp;
    const int lane = threadIdx.x & 31;
    const int h    = lane >> 2;

    const int beg = g_off[n], end = g_off[n + 1];

    float4 q4 = *(const float4*)(g_q + n * HIDDEN + lane * 4);
    const float wdh = Wd[h], bdh = bd[h];

    float  s = 0.f;
    float4 U = make_float4(0.f, 0.f, 0.f, 0.f);

    for (int j = beg; j < end; j++) {
        int e  = g_perm[j];
        int dn = dst[e];
        float4 k4 = *(const float4*)(g_k + dn * HIDDEN + lane * 4);
        float p = q4.x * k4.x + q4.y * k4.y + q4.z * k4.z + q4.w * k4.w;
        p += __shfl_xor_sync(0xffffffffu, p, 1);
        p += __shfl_xor_sync(0xffffffffu, p, 2);   // per-head dot, replicated in quad
        float dd = dist[e];
        float lg = p * 0.25f - (dd * dd * wdh + bdh);
        float ex = __expf(lg);
        if ((lane & 3) == 0) g_ex[e * 8 + h] = ex;
        s += ex;
        float4 v4 = *(const float4*)(g_v + dn * HIDDEN + lane * 4);
        U.x = fmaf(v4.x, ex, U.x);
        U.y = fmaf(v4.y, ex, U.y);
        U.z = fmaf(v4.z, ex, U.z);
        U.w = fmaf(v4.w, ex, U.w);
    }

    float inv = __frcp_rn(fmaxf(s, 1e-9f));
    U.x *= inv; U.y *= inv; U.z *= inv; U.w *= inv;
    *(float4*)(g_q + n * HIDDEN + lane * 4) = U;   // hupd in-place (only this warp touches row n)

    // displacement pass
    float xs   = (lane < 3) ? x[n * 3 + lane] : 0.f;
    float dacc = 0.f;
    for (int j = beg; j < end; j++) {
        int e  = g_perm[j];
        float ex  = g_ex[e * 8 + h];
        float val = ex * inv;                       // w for this head (x4 replicated)
#pragma unroll
        for (int off = 16; off; off >>= 1) val += __shfl_xor_sync(0xffffffffu, val, off);
        float wmean = val * (1.f / 32.f);           // = mean over 8 heads
        int dn = dst[e];
        if (lane < 3) dacc = fmaf(x[dn * 3 + lane] - xs, wmean, dacc);
    }
    if (lane < 3) g_disp[n * 3 + lane] = dacc;
}

// ---------------- gate + x_out ----------------
__global__ void k_gate(const float* __restrict__ Wg2, const float* __restrict__ bg2,
                       const float* __restrict__ x, float* __restrict__ out)
{
    int gt   = blockIdx.x * blockDim.x + threadIdx.x;
    int node = gt >> 5;
    int lane = threadIdx.x & 31;
    if (node >= N_NODES) return;

    float4 a = *(const float4*)(g_k + node * HIDDEN + lane * 4);  // t1
    float4 b = *(const float4*)(Wg2 + lane * 4);
    float p = a.x * b.x + a.y * b.y + a.z * b.z + a.w * b.w;
#pragma unroll
    for (int off = 16; off; off >>= 1) p += __shfl_xor_sync(0xffffffffu, p, off);
    float g = tanhf(p + bg2[0]);
    if (lane < 3) {
        out[N_NODES * HIDDEN + node * 3 + lane] =
            x[node * 3 + lane] + g * g_disp[node * 3 + lane];
    }
}

// ---------------- launch ----------------
extern "C" void kernel_launch(void* const* d_in, const int* in_sizes, int n_in,
                              void* d_out, int out_size)
{
    (void)in_sizes; (void)n_in; (void)out_size;
    const float* h    = (const float*)d_in[0];
    const float* x    = (const float*)d_in[1];
    const int*   src  = (const int*)  d_in[2];
    const int*   dst  = (const int*)  d_in[3];
    const float* dist = (const float*)d_in[4];
    const float* Wq = (const float*)d_in[5],  *bq = (const float*)d_in[6];
    const float* Wk = (const float*)d_in[7],  *bk = (const float*)d_in[8];
    const float* Wv = (const float*)d_in[9],  *bv = (const float*)d_in[10];
    const float* Wo = (const float*)d_in[11], *bo = (const float*)d_in[12];
    const float* Wd = (const float*)d_in[13], *bd = (const float*)d_in[14];
    const float* Wg1 = (const float*)d_in[15], *bg1 = (const float*)d_in[16];
    const float* Wg2 = (const float*)d_in[17], *bg2 = (const float*)d_in[18];
    float* out = (float*)d_out;

    void *pq, *pk, *pv;
    cudaGetSymbolAddress(&pq, g_q);
    cudaGetSymbolAddress(&pk, g_k);
    cudaGetSymbolAddress(&pv, g_v);
    float* fq = (float*)pq; float* fk = (float*)pk; float* fv = (float*)pv;

    const int B = 256;

    // counting sort of edges by src
    k_zero<<<(N_NODES + B - 1) / B, B>>>();
    k_hist<<<(N_EDGES + B - 1) / B, B>>>(src);
    k_scan<<<1, 1024>>>();
    k_scatter<<<(N_EDGES + B - 1) / B, B>>>(src);

    // fused QKV projection
    int gblocks = (N_NODES + 127) / 128;
    {
        dim3 grid(gblocks, 3);
        gemm128<0><<<grid, 256>>>(h, Wq, Wk, Wv, bq, bk, bv, nullptr, fq, fk, fv, N_NODES);
    }

    // warp-per-node attention + displacement (atomic-free)
    k_node<<<(N_NODES * 32 + B - 1) / B, B>>>(dst, dist, x, Wd, bd);

    // node phase
    {
        dim3 grid(gblocks, 1);
        gemm128<1><<<grid, 256>>>(fq, Wo, Wo, Wo, bo, bo, bo, h, out, out, out, N_NODES);      // h_out
        gemm128<2><<<grid, 256>>>(out, Wg1, Wg1, Wg1, bg1, bg1, bg1, nullptr, fk, fk, fk, N_NODES); // t1
    }
    k_gate<<<(N_NODES * 32 + B - 1) / B, B>>>(Wg2, bg2, x, out);
}

// round 6
// speedup vs baseline: 1.1353x; 1.1353x over previous
#include <cuda_runtime.h>
#include <cuda_bf16.h>
#include <cstdint>

#define N_NODES 50000
#define N_EDGES 500000
#define HIDDEN  128
#define HEADS   8
#define HDIM    16

// ---------------- static device scratch ----------------
__device__ float g_q[N_NODES * HIDDEN];     // q
__device__ float g_k[N_NODES * HIDDEN];     // k; later reused as t1 (silu output)
__device__ float g_v[N_NODES * HIDDEN];
__device__ float g_ex[N_EDGES * HEADS];     // exp(logit) per (edge, head)
__device__ float g_s[N_NODES * HEADS];
__device__ float g_U[N_NODES * HIDDEN];
__device__ float g_disp[N_NODES * 3];

__device__ __forceinline__ uint32_t smem_u32(const void* p) {
    uint32_t a;
    asm("{ .reg .u64 t; cvta.to.shared.u64 t, %1; cvt.u32.u64 %0, t; }" : "=r"(a) : "l"(p));
    return a;
}

// ---------------- init ----------------
__global__ void k_init() {
    int i = blockIdx.x * blockDim.x + threadIdx.x;
    float4 z = make_float4(0.f, 0.f, 0.f, 0.f);
    if (i < N_NODES * HIDDEN / 4) ((float4*)g_U)[i] = z;
    if (i < N_NODES * HEADS / 4) ((float4*)g_s)[i] = z;
    if (i < N_NODES * 3 / 4) ((float4*)g_disp)[i] = z;
}

// ---------------- split-bf16 HMMA GEMM: C[M,128] = A[M,128] @ W[128,128] ----------------
// D = Ah*Bh + Ah*Bl + Al*Bh (fp32 accum). EPI: 0 plain, 1 +residual, 2 silu.
// SCALE_A: A = g_U * rcp(max(g_s,1e-9)) on load (fuses hupd).
#define ASTR 136                       // bf16 row stride (272B, odd multiple of 16B)
#define SM_BF_TOTAL (4 * 128 * ASTR)   // Ah, Al, Bh, Bl
#define SM_BYTES (SM_BF_TOTAL * 2)

__device__ __forceinline__ void ldmat_x4(uint32_t* r, uint32_t addr) {
    asm volatile("ldmatrix.sync.aligned.m8n8.x4.shared.b16 {%0,%1,%2,%3}, [%4];"
                 : "=r"(r[0]), "=r"(r[1]), "=r"(r[2]), "=r"(r[3]) : "r"(addr));
}
__device__ __forceinline__ void ldmat_x2(uint32_t* r, uint32_t addr) {
    asm volatile("ldmatrix.sync.aligned.m8n8.x2.shared.b16 {%0,%1}, [%2];"
                 : "=r"(r[0]), "=r"(r[1]) : "r"(addr));
}
__device__ __forceinline__ void mma16816(float* c, const uint32_t* a, const uint32_t* b) {
    asm volatile("mma.sync.aligned.m16n8k16.row.col.f32.bf16.bf16.f32 "
                 "{%0,%1,%2,%3}, {%4,%5,%6,%7}, {%8,%9}, {%0,%1,%2,%3};"
                 : "+f"(c[0]), "+f"(c[1]), "+f"(c[2]), "+f"(c[3])
                 : "r"(a[0]), "r"(a[1]), "r"(a[2]), "r"(a[3]), "r"(b[0]), "r"(b[1]));
}

template <int EPI, bool SCALE_A>
__global__ __launch_bounds__(256, 1) void gemm_mma(
    const float* __restrict__ A,
    const float* __restrict__ B0, const float* __restrict__ B1, const float* __restrict__ B2,
    const float* __restrict__ bias0, const float* __restrict__ bias1, const float* __restrict__ bias2,
    const float* __restrict__ res,
    float* __restrict__ out0, float* __restrict__ out1, float* __restrict__ out2,
    int M)
{
    extern __shared__ __nv_bfloat16 sm[];
    __nv_bfloat16* Ah = sm;
    __nv_bfloat16* Al = Ah + 128 * ASTR;
    __nv_bfloat16* Bh = Al + 128 * ASTR;
    __nv_bfloat16* Bl = Bh + 128 * ASTR;

    const float* W    = (blockIdx.y == 0) ? B0    : (blockIdx.y == 1) ? B1    : B2;
    const float* bias = (blockIdx.y == 0) ? bias0 : (blockIdx.y == 1) ? bias1 : bias2;
    float*       out  = (blockIdx.y == 0) ? out0  : (blockIdx.y == 1) ? out1  : out2;

    const int t = threadIdx.x, wid = t >> 5, lane = t & 31;
    const int row0 = blockIdx.x * 128;

    // ---- load A tile (fp32 -> hi/lo bf16) ----
    for (int i = t; i < 4096; i += 256) {
        int r = i >> 5, col = (i & 31) * 4;
        int gr = row0 + r;
        float4 a = make_float4(0.f, 0.f, 0.f, 0.f);
        if (gr < M) {
            a = *(const float4*)(A + gr * HIDDEN + col);
            if (SCALE_A) {
                float inv = __frcp_rn(fmaxf(g_s[gr * HEADS + (col >> 4)], 1e-9f));
                a.x *= inv; a.y *= inv; a.z *= inv; a.w *= inv;
            }
        }
        __nv_bfloat16 h0 = __float2bfloat16_rn(a.x), h1 = __float2bfloat16_rn(a.y);
        __nv_bfloat16 h2 = __float2bfloat16_rn(a.z), h3 = __float2bfloat16_rn(a.w);
        __nv_bfloat16 l0 = __float2bfloat16_rn(a.x - __bfloat162float(h0));
        __nv_bfloat16 l1 = __float2bfloat16_rn(a.y - __bfloat162float(h1));
        __nv_bfloat16 l2 = __float2bfloat16_rn(a.z - __bfloat162float(h2));
        __nv_bfloat16 l3 = __float2bfloat16_rn(a.w - __bfloat162float(h3));
        int base = r * ASTR + col;
        *(__nv_bfloat162*)(Ah + base)     = __nv_bfloat162(h0, h1);
        *(__nv_bfloat162*)(Ah + base + 2) = __nv_bfloat162(h2, h3);
        *(__nv_bfloat162*)(Al + base)     = __nv_bfloat162(l0, l1);
        *(__nv_bfloat162*)(Al + base + 2) = __nv_bfloat162(l2, l3);
    }

    // ---- load B tile transposed: Bt[n][k] = W[k][n], hi/lo ----
    for (int i = t; i < 4096; i += 256) {
        int n = i & 127, k0 = (i >> 7) * 4;
#pragma unroll
        for (int j = 0; j < 4; j++) {
            float w = W[(k0 + j) * HIDDEN + n];
            __nv_bfloat16 hh = __float2bfloat16_rn(w);
            __nv_bfloat16 ll = __float2bfloat16_rn(w - __bfloat162float(hh));
            Bh[n * ASTR + k0 + j] = hh;
            Bl[n * ASTR + k0 + j] = ll;
        }
    }
    __syncthreads();

    // ---- compute: warp = 64x32 subtile (wm: 0..1 m, wn: 0..3 n) ----
    const int wm = wid & 1, wn = wid >> 1;
    float acc[4][4][4];
#pragma unroll
    for (int mt = 0; mt < 4; mt++)
#pragma unroll
        for (int nt = 0; nt < 4; nt++)
#pragma unroll
            for (int q = 0; q < 4; q++) acc[mt][nt][q] = 0.f;

    const int arow = (lane & 15), acolh = (lane >> 4) * 8;
    const int brow = (lane & 7),  bcolh = ((lane >> 3) & 1) * 8;

#pragma unroll
    for (int p = 0; p < 3; p++) {
        const __nv_bfloat16* Ab = (p == 2) ? Al : Ah;
        const __nv_bfloat16* Bb = (p == 1) ? Bl : Bh;
#pragma unroll
        for (int ks = 0; ks < 8; ks++) {
            int kc = ks * 16;
            uint32_t afr[4][4];
#pragma unroll
            for (int mt = 0; mt < 4; mt++) {
                int row = wm * 64 + mt * 16 + arow;
                ldmat_x4(afr[mt], smem_u32(Ab + row * ASTR + kc + acolh));
            }
            uint32_t bfr[4][2];
#pragma unroll
            for (int nt = 0; nt < 4; nt++) {
                int row = wn * 32 + nt * 8 + brow;
                ldmat_x2(bfr[nt], smem_u32(Bb + row * ASTR + kc + bcolh));
            }
#pragma unroll
            for (int mt = 0; mt < 4; mt++)
#pragma unroll
                for (int nt = 0; nt < 4; nt++)
                    mma16816(acc[mt][nt], afr[mt], bfr[nt]);
        }
    }

    // ---- epilogue ----
    const int g = lane >> 2, tid2 = lane & 3;
#pragma unroll
    for (int mt = 0; mt < 4; mt++) {
#pragma unroll
        for (int half = 0; half < 2; half++) {
            int gr = row0 + wm * 64 + mt * 16 + half * 8 + g;
            if (gr >= M) continue;
#pragma unroll
            for (int nt = 0; nt < 4; nt++) {
                int col = wn * 32 + nt * 8 + tid2 * 2;
                float z0 = acc[mt][nt][half * 2 + 0] + bias[col];
                float z1 = acc[mt][nt][half * 2 + 1] + bias[col + 1];
                if (EPI == 1) {
                    float2 r2 = *(const float2*)(res + gr * HIDDEN + col);
                    z0 += r2.x; z1 += r2.y;
                }
                if (EPI == 2) {
                    z0 = z0 / (1.f + __expf(-z0));
                    z1 = z1 / (1.f + __expf(-z1));
                }
                *(float2*)(out + gr * HIDDEN + col) = make_float2(z0, z1);
            }
        }
    }
}

// ---------------- fused edge kernel (R3, best known) ----------------
__global__ void k_edge(const int* __restrict__ src, const int* __restrict__ dst,
                       const float* __restrict__ dist,
                       const float* __restrict__ Wd, const float* __restrict__ bd)
{
    int t = blockIdx.x * blockDim.x + threadIdx.x;
    if (t >= N_EDGES * HEADS) return;
    int e = t >> 3, h = t & 7;
    int sn = src[e], dn = dst[e];

    const float4* qp = (const float4*)(g_q + sn * HIDDEN + h * HDIM);
    const float4* kp = (const float4*)(g_k + dn * HIDDEN + h * HDIM);
    float acc = 0.f;
#pragma unroll
    for (int i = 0; i < 4; i++) {
        float4 a = qp[i], b = kp[i];
        acc += a.x * b.x + a.y * b.y + a.z * b.z + a.w * b.w;
    }
    float dd = dist[e];
    float lg = acc * 0.25f - (dd * dd * Wd[h] + bd[h]);
    float ex = __expf(lg);
    g_ex[t] = ex;

    atomicAdd(&g_s[sn * HEADS + h], ex);

    const float4* vp = (const float4*)(g_v + dn * HIDDEN + h * HDIM);
    float* up = g_U + sn * HIDDEN + h * HDIM;
#pragma unroll
    for (int i = 0; i < 4; i++) {
        float4 vv = vp[i];
        float x0 = vv.x * ex, x1 = vv.y * ex, x2 = vv.z * ex, x3 = vv.w * ex;
        asm volatile("red.global.add.v4.f32 [%0], {%1,%2,%3,%4};"
                     :: "l"(up + i * 4), "f"(x0), "f"(x1), "f"(x2), "f"(x3)
                     : "memory");
    }
}

// ---------------- displacement scatter ----------------
__global__ void k_disp(const int* __restrict__ src, const int* __restrict__ dst,
                       const float* __restrict__ x)
{
    int e = blockIdx.x * blockDim.x + threadIdx.x;
    if (e >= N_EDGES) return;
    int sn = src[e], dn = dst[e];

    const float4* exp4 = (const float4*)(g_ex + e * 8);
    const float4* sp   = (const float4*)(g_s + sn * 8);
    float4 e0 = exp4[0], e1 = exp4[1];
    float4 s0 = sp[0],   s1 = sp[1];

    float wsum =
        e0.x / fmaxf(s0.x, 1e-9f) + e0.y / fmaxf(s0.y, 1e-9f) +
        e0.z / fmaxf(s0.z, 1e-9f) + e0.w / fmaxf(s0.w, 1e-9f) +
        e1.x / fmaxf(s1.x, 1e-9f) + e1.y / fmaxf(s1.y, 1e-9f) +
        e1.z / fmaxf(s1.z, 1e-9f) + e1.w / fmaxf(s1.w, 1e-9f);
    float wmean = wsum * 0.125f;

#pragma unroll
    for (int c = 0; c < 3; c++)
        atomicAdd(&g_disp[sn * 3 + c], (x[dn * 3 + c] - x[sn * 3 + c]) * wmean);
}

// ---------------- gate + x_out ----------------
__global__ void k_gate(const float* __restrict__ Wg2, const float* __restrict__ bg2,
                       const float* __restrict__ x, float* __restrict__ out)
{
    int gt   = blockIdx.x * blockDim.x + threadIdx.x;
    int node = gt >> 5;
    int lane = threadIdx.x & 31;
    if (node >= N_NODES) return;

    float4 a = *(const float4*)(g_k + node * HIDDEN + lane * 4);  // t1
    float4 b = *(const float4*)(Wg2 + lane * 4);
    float p = a.x * b.x + a.y * b.y + a.z * b.z + a.w * b.w;
#pragma unroll
    for (int off = 16; off; off >>= 1) p += __shfl_xor_sync(0xffffffffu, p, off);
    float g = tanhf(p + bg2[0]);
    if (lane < 3) {
        out[N_NODES * HIDDEN + node * 3 + lane] =
            x[node * 3 + lane] + g * g_disp[node * 3 + lane];
    }
}

// ---------------- launch ----------------
extern "C" void kernel_launch(void* const* d_in, const int* in_sizes, int n_in,
                              void* d_out, int out_size)
{
    (void)in_sizes; (void)n_in; (void)out_size;
    const float* h    = (const float*)d_in[0];
    const float* x    = (const float*)d_in[1];
    const int*   src  = (const int*)  d_in[2];
    const int*   dst  = (const int*)  d_in[3];
    const float* dist = (const float*)d_in[4];
    const float* Wq = (const float*)d_in[5],  *bq = (const float*)d_in[6];
    const float* Wk = (const float*)d_in[7],  *bk = (const float*)d_in[8];
    const float* Wv = (const float*)d_in[9],  *bv = (const float*)d_in[10];
    const float* Wo = (const float*)d_in[11], *bo = (const float*)d_in[12];
    const float* Wd = (const float*)d_in[13], *bd = (const float*)d_in[14];
    const float* Wg1 = (const float*)d_in[15], *bg1 = (const float*)d_in[16];
    const float* Wg2 = (const float*)d_in[17], *bg2 = (const float*)d_in[18];
    float* out = (float*)d_out;

    void *pq, *pk, *pv, *pU;
    cudaGetSymbolAddress(&pq, g_q);
    cudaGetSymbolAddress(&pk, g_k);
    cudaGetSymbolAddress(&pv, g_v);
    cudaGetSymbolAddress(&pU, g_U);
    float* fq = (float*)pq; float* fk = (float*)pk; float* fv = (float*)pv;
    float* fU = (float*)pU;

    cudaFuncSetAttribute(gemm_mma<0, false>, cudaFuncAttributeMaxDynamicSharedMemorySize, SM_BYTES);
    cudaFuncSetAttribute(gemm_mma<1, true>,  cudaFuncAttributeMaxDynamicSharedMemorySize, SM_BYTES);
    cudaFuncSetAttribute(gemm_mma<2, false>, cudaFuncAttributeMaxDynamicSharedMemorySize, SM_BYTES);

    const int B = 256;
    k_init<<<(N_NODES * HIDDEN / 4 + B - 1) / B, B>>>();

    int gblocks = (N_NODES + 127) / 128;
    // fused QKV projection (HMMA split-bf16)
    {
        dim3 grid(gblocks, 3);
        gemm_mma<0, false><<<grid, 256, SM_BYTES>>>(h, Wq, Wk, Wv, bq, bk, bv,
                                                    nullptr, fq, fk, fv, N_NODES);
    }

    // edge phase (atomic scatter — best known)
    int eht = N_EDGES * HEADS;
    k_edge<<<(eht + B - 1) / B, B>>>(src, dst, dist, Wd, bd);
    k_disp<<<(N_EDGES + B - 1) / B, B>>>(src, dst, x);

    // Wo GEMM reads g_U and normalizes by s on the fly (k_hupd fused away)
    {
        dim3 grid(gblocks, 1);
        gemm_mma<1, true><<<grid, 256, SM_BYTES>>>(fU, Wo, Wo, Wo, bo, bo, bo,
                                                   h, out, out, out, N_NODES);
        gemm_mma<2, false><<<grid, 256, SM_BYTES>>>(out, Wg1, Wg1, Wg1, bg1, bg1, bg1,
                                                    nullptr, fk, fk, fk, N_NODES);
    }
    k_gate<<<(N_NODES * 32 + B - 1) / B, B>>>(Wg2, bg2, x, out);
}

// round 7
// speedup vs baseline: 1.2064x; 1.0626x over previous
#include <cuda_runtime.h>
#include <cuda_bf16.h>
#include <cstdint>

#define N_NODES 50000
#define N_EDGES 500000
#define HIDDEN  128
#define HEADS   8
#define HDIM    16

// ---------------- static device scratch ----------------
__device__ float g_q[N_NODES * HIDDEN];     // q
__device__ float g_k[N_NODES * HIDDEN];     // k; later reused as t1 (silu output)
__device__ float g_v[N_NODES * HIDDEN];
__device__ float g_ex[N_EDGES * HEADS];     // exp(logit) per (edge, head)
__device__ float g_s[N_NODES * HEADS];
__device__ float g_U[N_NODES * HIDDEN];
__device__ float g_disp[N_NODES * 3];

// ---------------- init ----------------
__global__ void k_init() {
    int i = blockIdx.x * blockDim.x + threadIdx.x;
    float4 z = make_float4(0.f, 0.f, 0.f, 0.f);
    if (i < N_NODES * HIDDEN / 4) ((float4*)g_U)[i] = z;
    if (i < N_NODES * HEADS / 4) ((float4*)g_s)[i] = z;
    if (i < N_NODES * 3 / 4) ((float4*)g_disp)[i] = z;
}

// ---------------- packed-f32x2 GEMM: C[M,128] = A[M,128] @ W[128,128] ----------------
// 128x128 CTA tile, 256 thr, 8x8 microtile; inner loop uses fma.rn.f32x2 (FFMA2).
// EPI: 0 plain, 1 +residual, 2 silu. SCALE_A: A row r scaled by rcp(max(g_s[r,head],1e-9)).
#define KC 16

__device__ __forceinline__ uint64_t pack_dup(float a) {
    uint64_t r;
    asm("mov.b64 %0, {%1, %1};" : "=l"(r) : "f"(a));
    return r;
}
__device__ __forceinline__ void fma2(uint64_t& c, uint64_t a, uint64_t b) {
    asm("fma.rn.f32x2 %0, %1, %2, %0;" : "+l"(c) : "l"(a), "l"(b));
}
__device__ __forceinline__ float2 unpack2(uint64_t p) {
    float lo, hi;
    asm("mov.b64 {%0, %1}, %2;" : "=f"(lo), "=f"(hi) : "l"(p));
    return make_float2(lo, hi);
}

template <int EPI, bool SCALE_A>
__global__ __launch_bounds__(256, 2) void gemm128(
    const float* __restrict__ A,
    const float* __restrict__ B0, const float* __restrict__ B1, const float* __restrict__ B2,
    const float* __restrict__ bias0, const float* __restrict__ bias1, const float* __restrict__ bias2,
    const float* __restrict__ res,
    float* __restrict__ out0, float* __restrict__ out1, float* __restrict__ out2,
    int M)
{
    __shared__ float As[KC][132];     // transposed: As[k][m]
    __shared__ float Bs[KC][HIDDEN];

    const float* B    = (blockIdx.y == 0) ? B0    : (blockIdx.y == 1) ? B1    : B2;
    const float* bias = (blockIdx.y == 0) ? bias0 : (blockIdx.y == 1) ? bias1 : bias2;
    float*       out  = (blockIdx.y == 0) ? out0  : (blockIdx.y == 1) ? out1  : out2;

    const int t   = threadIdx.x;
    const int tx  = t & 15;           // col group (8 cols = 4 packed pairs)
    const int ty  = t >> 4;           // row group (8 rows)
    const int row0 = blockIdx.x * 128;

    uint64_t acc[8][4];               // 8 rows x 4 col-pairs, packed f32x2
#pragma unroll
    for (int i = 0; i < 8; i++)
#pragma unroll
        for (int j = 0; j < 4; j++) acc[i][j] = 0ull;

    for (int kt = 0; kt < HIDDEN; kt += KC) {
        // A tile: 128 rows x 16 k, stored transposed
#pragma unroll
        for (int it = 0; it < 2; it++) {
            int idx = t + it * 256;
            int r   = idx >> 2;
            int c4  = idx & 3;
            float4 val = make_float4(0.f, 0.f, 0.f, 0.f);
            int gr = row0 + r;
            if (gr < M) {
                val = *(const float4*)(A + gr * HIDDEN + kt + c4 * 4);
                if (SCALE_A) {
                    float inv = __frcp_rn(fmaxf(g_s[gr * HEADS + ((kt + c4 * 4) >> 4)], 1e-9f));
                    val.x *= inv; val.y *= inv; val.z *= inv; val.w *= inv;
                }
            }
            As[c4 * 4 + 0][r] = val.x;
            As[c4 * 4 + 1][r] = val.y;
            As[c4 * 4 + 2][r] = val.z;
            As[c4 * 4 + 3][r] = val.w;
        }
        // B tile: 16 x 128
#pragma unroll
        for (int it = 0; it < 2; it++) {
            int idx = t + it * 256;
            int r   = idx >> 5;
            int c4  = idx & 31;
            *(float4*)(&Bs[r][c4 * 4]) = *(const float4*)(B + (kt + r) * HIDDEN + c4 * 4);
        }
        __syncthreads();

#pragma unroll
        for (int kk = 0; kk < KC; kk++) {
            float4 a0 = *(float4*)(&As[kk][ty * 8]);
            float4 a1 = *(float4*)(&As[kk][ty * 8 + 4]);
            // b pairs: reinterpret 16B loads as 2 packed f32x2 each (adjacent cols)
            ulonglong2 b01 = *(ulonglong2*)(&Bs[kk][tx * 8]);
            ulonglong2 b23 = *(ulonglong2*)(&Bs[kk][tx * 8 + 4]);
            uint64_t bp[4] = {b01.x, b01.y, b23.x, b23.y};
            uint64_t ap[8];
            ap[0] = pack_dup(a0.x); ap[1] = pack_dup(a0.y);
            ap[2] = pack_dup(a0.z); ap[3] = pack_dup(a0.w);
            ap[4] = pack_dup(a1.x); ap[5] = pack_dup(a1.y);
            ap[6] = pack_dup(a1.z); ap[7] = pack_dup(a1.w);
#pragma unroll
            for (int i = 0; i < 8; i++)
#pragma unroll
                for (int j = 0; j < 4; j++) fma2(acc[i][j], ap[i], bp[j]);
        }
        __syncthreads();
    }

    // epilogue: 8 rows x 8 cols per thread
#pragma unroll
    for (int i = 0; i < 8; i++) {
        int gr = row0 + ty * 8 + i;
        if (gr >= M) continue;
#pragma unroll
        for (int jj = 0; jj < 2; jj++) {
            int col = tx * 8 + jj * 4;
            float2 p0 = unpack2(acc[i][jj * 2 + 0]);
            float2 p1 = unpack2(acc[i][jj * 2 + 1]);
            float z[4] = {p0.x, p0.y, p1.x, p1.y};
#pragma unroll
            for (int q = 0; q < 4; q++) z[q] += bias[col + q];
            if (EPI == 1) {
                float4 r4 = *(const float4*)(res + gr * HIDDEN + col);
                z[0] += r4.x; z[1] += r4.y; z[2] += r4.z; z[3] += r4.w;
            }
            if (EPI == 2) {
#pragma unroll
                for (int q = 0; q < 4; q++) z[q] = z[q] / (1.f + __expf(-z[q]));
            }
            *(float4*)(out + gr * HIDDEN + col) = make_float4(z[0], z[1], z[2], z[3]);
        }
    }
}

// ---------------- fused edge kernel: logits + exp + s-sum + U scatter ----------------
__global__ void k_edge(const int* __restrict__ src, const int* __restrict__ dst,
                       const float* __restrict__ dist,
                       const float* __restrict__ Wd, const float* __restrict__ bd)
{
    int t = blockIdx.x * blockDim.x + threadIdx.x;
    if (t >= N_EDGES * HEADS) return;
    int e = t >> 3, h = t & 7;
    int sn = src[e], dn = dst[e];

    const float4* qp = (const float4*)(g_q + sn * HIDDEN + h * HDIM);
    const float4* kp = (const float4*)(g_k + dn * HIDDEN + h * HDIM);
    float acc = 0.f;
#pragma unroll
    for (int i = 0; i < 4; i++) {
        float4 a = qp[i], b = kp[i];
        acc += a.x * b.x + a.y * b.y + a.z * b.z + a.w * b.w;
    }
    float dd = dist[e];
    float lg = acc * 0.25f - (dd * dd * Wd[h] + bd[h]);
    float ex = __expf(lg);
    g_ex[t] = ex;

    atomicAdd(&g_s[sn * HEADS + h], ex);

    const float4* vp = (const float4*)(g_v + dn * HIDDEN + h * HDIM);
    float* up = g_U + sn * HIDDEN + h * HDIM;
#pragma unroll
    for (int i = 0; i < 4; i++) {
        float4 vv = vp[i];
        float x0 = vv.x * ex, x1 = vv.y * ex, x2 = vv.z * ex, x3 = vv.w * ex;
        asm volatile("red.global.add.v4.f32 [%0], {%1,%2,%3,%4};"
                     :: "l"(up + i * 4), "f"(x0), "f"(x1), "f"(x2), "f"(x3)
                     : "memory");
    }
}

// ---------------- displacement scatter ----------------
__global__ void k_disp(const int* __restrict__ src, const int* __restrict__ dst,
                       const float* __restrict__ x)
{
    int e = blockIdx.x * blockDim.x + threadIdx.x;
    if (e >= N_EDGES) return;
    int sn = src[e], dn = dst[e];

    const float4* exp4 = (const float4*)(g_ex + e * 8);
    const float4* sp   = (const float4*)(g_s + sn * 8);
    float4 e0 = exp4[0], e1 = exp4[1];
    float4 s0 = sp[0],   s1 = sp[1];

    float wsum =
        e0.x / fmaxf(s0.x, 1e-9f) + e0.y / fmaxf(s0.y, 1e-9f) +
        e0.z / fmaxf(s0.z, 1e-9f) + e0.w / fmaxf(s0.w, 1e-9f) +
        e1.x / fmaxf(s1.x, 1e-9f) + e1.y / fmaxf(s1.y, 1e-9f) +
        e1.z / fmaxf(s1.z, 1e-9f) + e1.w / fmaxf(s1.w, 1e-9f);
    float wmean = wsum * 0.125f;

#pragma unroll
    for (int c = 0; c < 3; c++)
        atomicAdd(&g_disp[sn * 3 + c], (x[dn * 3 + c] - x[sn * 3 + c]) * wmean);
}

// ---------------- gate + x_out ----------------
__global__ void k_gate(const float* __restrict__ Wg2, const float* __restrict__ bg2,
                       const float* __restrict__ x, float* __restrict__ out)
{
    int gt   = blockIdx.x * blockDim.x + threadIdx.x;
    int node = gt >> 5;
    int lane = threadIdx.x & 31;
    if (node >= N_NODES) return;

    float4 a = *(const float4*)(g_k + node * HIDDEN + lane * 4);  // t1
    float4 b = *(const float4*)(Wg2 + lane * 4);
    float p = a.x * b.x + a.y * b.y + a.z * b.z + a.w * b.w;
#pragma unroll
    for (int off = 16; off; off >>= 1) p += __shfl_xor_sync(0xffffffffu, p, off);
    float g = tanhf(p + bg2[0]);
    if (lane < 3) {
        out[N_NODES * HIDDEN + node * 3 + lane] =
            x[node * 3 + lane] + g * g_disp[node * 3 + lane];
    }
}

// ---------------- launch ----------------
extern "C" void kernel_launch(void* const* d_in, const int* in_sizes, int n_in,
                              void* d_out, int out_size)
{
    (void)in_sizes; (void)n_in; (void)out_size;
    const float* h    = (const float*)d_in[0];
    const float* x    = (const float*)d_in[1];
    const int*   src  = (const int*)  d_in[2];
    const int*   dst  = (const int*)  d_in[3];
    const float* dist = (const float*)d_in[4];
    const float* Wq = (const float*)d_in[5],  *bq = (const float*)d_in[6];
    const float* Wk = (const float*)d_in[7],  *bk = (const float*)d_in[8];
    const float* Wv = (const float*)d_in[9],  *bv = (const float*)d_in[10];
    const float* Wo = (const float*)d_in[11], *bo = (const float*)d_in[12];
    const float* Wd = (const float*)d_in[13], *bd = (const float*)d_in[14];
    const float* Wg1 = (const float*)d_in[15], *bg1 = (const float*)d_in[16];
    const float* Wg2 = (const float*)d_in[17], *bg2 = (const float*)d_in[18];
    float* out = (float*)d_out;

    void *pq, *pk, *pv, *pU;
    cudaGetSymbolAddress(&pq, g_q);
    cudaGetSymbolAddress(&pk, g_k);
    cudaGetSymbolAddress(&pv, g_v);
    cudaGetSymbolAddress(&pU, g_U);
    float* fq = (float*)pq; float* fk = (float*)pk; float* fv = (float*)pv;
    float* fU = (float*)pU;

    const int B = 256;
    k_init<<<(N_NODES * HIDDEN / 4 + B - 1) / B, B>>>();

    // fused QKV projection (FFMA2)
    int gblocks = (N_NODES + 127) / 128;
    {
        dim3 grid(gblocks, 3);
        gemm128<0, false><<<grid, 256>>>(h, Wq, Wk, Wv, bq, bk, bv,
                                         nullptr, fq, fk, fv, N_NODES);
    }

    // edge phase (atomic scatter — best known)
    int eht = N_EDGES * HEADS;
    k_edge<<<(eht + B - 1) / B, B>>>(src, dst, dist, Wd, bd);
    k_disp<<<(N_EDGES + B - 1) / B, B>>>(src, dst, x);

    // Wo GEMM normalizes g_U by rcp(s) on the fly (k_hupd fused away)
    {
        dim3 grid(gblocks, 1);
        gemm128<1, true><<<grid, 256>>>(fU, Wo, Wo, Wo, bo, bo, bo,
                                        h, out, out, out, N_NODES);
        gemm128<2, false><<<grid, 256>>>(out, Wg1, Wg1, Wg1, bg1, bg1, bg1,
                                         nullptr, fk, fk, fk, N_NODES);
    }
    k_gate<<<(N_NODES * 32 + B - 1) / B, B>>>(Wg2, bg2, x, out);
}